// round 11
// baseline (speedup 1.0000x reference)
#include <cuda_runtime.h>
#include <cuda_bf16.h>
#include <math.h>
#include <stdint.h>

// ---------------- problem constants ----------------
#define NT      32768
#define NPER    2048
#define IN_C    256
#define DIM     128
#define H1DIM   256
#define NATOMS  20
#define ENC_H   100
#define OUTC    6
#define MASK_WORDS (NT * 64)

// ---------------- scratch ----------------
__device__ unsigned g_mask[MASK_WORDS];
__device__ float    g_stats[2 * IN_C];
__device__ int      g_ids[NT];
__device__ float    g_b1f[H1DIM];
__device__ float    g_W1f[IN_C * H1DIM];   // BN-folded W1 (GEMM1 B operand)
__device__ float    g_TW[NATOMS * DIM];
__device__ float    g_A1p[128 * 128];      // A1 zero-padded 100->128 cols
__device__ float    g_a1p[128];
__device__ float    g_h1[(size_t)NT * H1DIM];

// ---------------- helpers ----------------
__device__ __forceinline__ float gelu(float x) {
    return 0.5f * x * (1.0f + erff(x * 0.70710678118654752f));
}

// ---------------- K0: zero mask + stats ----------------
__global__ void k_zero() {
    int i = blockIdx.x * blockDim.x + threadIdx.x;
    if (i < MASK_WORDS) g_mask[i] = 0u;
    if (i < 2 * IN_C)   g_stats[i] = 0.0f;
}

// ---------------- K1: BN stats ----------------
__global__ void k_bn_stats(const float* __restrict__ x) {
    int c  = threadIdx.x;
    int r0 = blockIdx.x * 128;
    float s = 0.f, q = 0.f;
    #pragma unroll 4
    for (int r = 0; r < 128; r++) {
        float v = x[(size_t)(r0 + r) * IN_C + c];
        s += v; q += v * v;
    }
    atomicAdd(&g_stats[c], s);
    atomicAdd(&g_stats[IN_C + c], q);
}

// ---------------- K2: fold BN into W1 ----------------
__global__ void k_fold(const float* __restrict__ W1, const float* __restrict__ b1,
                       const float* __restrict__ gamma, const float* __restrict__ beta) {
    int j = blockIdx.x;      // output col
    int c = threadIdx.x;     // input channel
    float mean = g_stats[c] * (1.0f / NT);
    float var  = g_stats[IN_C + c] * (1.0f / NT) - mean * mean;
    float inv  = rsqrtf(var + 1e-5f);
    float sc   = gamma[c] * inv;
    float sh   = beta[c] - mean * sc;
    float w    = W1[c * H1DIM + j];
    g_W1f[c * H1DIM + j] = sc * w;
    __shared__ float red[256];
    red[c] = sh * w;
    __syncthreads();
    for (int o = 128; o > 0; o >>= 1) {
        if (c < o) red[c] += red[c + o];
        __syncthreads();
    }
    if (c == 0) g_b1f[j] = b1[j] + red[0];
}

// ---------------- K3: TW = embed@W_msg (blocks 0..319) + pad A1 (blocks 320..383) ----------------
__global__ void k_small(const float* __restrict__ embed, const float* __restrict__ Wm,
                        const float* __restrict__ A1, const float* __restrict__ a1) {
    if (blockIdx.x < 320) {
        int w = (blockIdx.x * blockDim.x + threadIdx.x) >> 5;
        int lane = threadIdx.x & 31;
        if (w < NATOMS * DIM) {
            int a = w >> 7, j = w & 127;
            float s = 0.f;
            #pragma unroll
            for (int i = 0; i < 4; i++) {
                int k = lane * 4 + i;
                s += embed[a * DIM + k] * Wm[k * DIM + j];
            }
            #pragma unroll
            for (int o = 16; o > 0; o >>= 1) s += __shfl_xor_sync(0xffffffffu, s, o);
            if (lane == 0) g_TW[w] = s;
        }
    } else {
        int t = (blockIdx.x - 320) * blockDim.x + threadIdx.x;
        if (t < 128 * 128) {
            int k = t >> 7, j = t & 127;
            g_A1p[t] = (j < ENC_H) ? A1[k * ENC_H + j] : 0.0f;
            if (k == 0) g_a1p[j] = (j < ENC_H) ? a1[j] : 0.0f;
        }
    }
}

// ---------------- K4: edge scatter ----------------
__global__ void k_edges(const int* __restrict__ ei, int E) {
    int e = blockIdx.x * blockDim.x + threadIdx.x;
    if (e < E) {
        int s = ei[e];
        int d = ei[E + e];
        if ((s >> 11) == (d >> 11)) {
            unsigned bit = ((unsigned)s << 11) + (unsigned)(d & (NPER - 1));
            atomicOr(&g_mask[bit >> 5], 1u << (bit & 31));
        }
    }
}

// ---------------- fused SGEMM (BM=BN=128, BK=16, TM=TN=8, reg double-buffer) ----------------
// EPI 0: C = gelu(A@B + bias)            (GEMM1 -> g_h1)
// EPI 1: two-pass 64-row epilogue (hbuf overlaps As/Bs): logits -> argmax -> g_ids
// EPI 2: two-pass 64-row epilogue: t2 = gelu(t1[:,0:100]@A2+a2); dyt; tanh -> OUT
template<int EPI>
__global__ void __launch_bounds__(256)
k_gemm(const float* __restrict__ A, const float* __restrict__ B,
       const float* __restrict__ bias, float* __restrict__ C,
       const float* __restrict__ X0, const float* __restrict__ X1,
       const float* __restrict__ X2, const float* __restrict__ X3,
       const float* __restrict__ X4, float* __restrict__ OUT,
       int K, int N) {
    extern __shared__ float sm[];
    float* As = sm;                // 16*128  (dead after mainloop)
    float* Bs = sm + 2048;         // 16*128  (dead after mainloop)

    int tid = threadIdx.x;
    int nt = blockIdx.x, mt = blockIdx.y;
    const float* Ab = A + (size_t)mt * 128 * K;
    const float* Bb = B + nt * 128;
    const float* bb = bias + nt * 128;

    int arow = tid >> 1, acol = (tid & 1) * 8;
    int brow = tid >> 4, bcol = (tid & 15) * 8;
    int tr = (tid >> 4) * 8, tc = (tid & 15) * 8;

    float acc[8][8];
    #pragma unroll
    for (int i = 0; i < 8; i++)
        #pragma unroll
        for (int j = 0; j < 8; j++) acc[i][j] = 0.f;

    // prefetch first k-tile into registers
    float4 pav0 = *(const float4*)(Ab + (size_t)arow * K + acol);
    float4 pav1 = *(const float4*)(Ab + (size_t)arow * K + acol + 4);
    float4 pbv0 = *(const float4*)(Bb + (size_t)brow * N + bcol);
    float4 pbv1 = *(const float4*)(Bb + (size_t)brow * N + bcol + 4);

    for (int k0 = 0; k0 < K; k0 += 16) {
        As[(acol + 0) * 128 + arow] = pav0.x;
        As[(acol + 1) * 128 + arow] = pav0.y;
        As[(acol + 2) * 128 + arow] = pav0.z;
        As[(acol + 3) * 128 + arow] = pav0.w;
        As[(acol + 4) * 128 + arow] = pav1.x;
        As[(acol + 5) * 128 + arow] = pav1.y;
        As[(acol + 6) * 128 + arow] = pav1.z;
        As[(acol + 7) * 128 + arow] = pav1.w;
        *(float4*)&Bs[brow * 128 + bcol]     = pbv0;
        *(float4*)&Bs[brow * 128 + bcol + 4] = pbv1;
        __syncthreads();

        if (k0 + 16 < K) {
            pav0 = *(const float4*)(Ab + (size_t)arow * K + k0 + 16 + acol);
            pav1 = *(const float4*)(Ab + (size_t)arow * K + k0 + 16 + acol + 4);
            pbv0 = *(const float4*)(Bb + (size_t)(k0 + 16 + brow) * N + bcol);
            pbv1 = *(const float4*)(Bb + (size_t)(k0 + 16 + brow) * N + bcol + 4);
        }

        #pragma unroll
        for (int kk = 0; kk < 16; kk++) {
            float4 a0 = *(const float4*)&As[kk * 128 + tr];
            float4 a1 = *(const float4*)&As[kk * 128 + tr + 4];
            float4 b0 = *(const float4*)&Bs[kk * 128 + tc];
            float4 b1 = *(const float4*)&Bs[kk * 128 + tc + 4];
            float ra[8] = {a0.x, a0.y, a0.z, a0.w, a1.x, a1.y, a1.z, a1.w};
            float rb[8] = {b0.x, b0.y, b0.z, b0.w, b1.x, b1.y, b1.z, b1.w};
            #pragma unroll
            for (int i = 0; i < 8; i++)
                #pragma unroll
                for (int j = 0; j < 8; j++) acc[i][j] += ra[i] * rb[j];
        }
        __syncthreads();
    }

    // ---- epilogue ----
    if (EPI == 0) {
        #pragma unroll
        for (int i = 0; i < 8; i++) {
            int row = tr + i;
            float o[8];
            #pragma unroll
            for (int j = 0; j < 8; j++) o[j] = gelu(acc[i][j] + bb[tc + j]);
            float* crow = C + (size_t)(mt * 128 + row) * N + nt * 128 + tc;
            *(float4*)(crow)     = make_float4(o[0], o[1], o[2], o[3]);
            *(float4*)(crow + 4) = make_float4(o[4], o[5], o[6], o[7]);
        }
    } else {
        // two-pass 64-row epilogue; hbuf OVERLAPS As/Bs (dead now)
        const int HS = 132;                // stride: /4 aligned, conflict-free
        float* hbuf = sm;                  // 64 * 132 = 8448 floats
        float* aux  = sm + 64 * HS;

        if (EPI == 1) {
            for (int i = tid; i < 128 * NATOMS; i += 256) aux[i] = X0[i];        // W3s
            if (tid < NATOMS) aux[2560 + tid] = X1[tid];                          // b3s
        }
        if (EPI == 2) {
            for (int i = tid; i < ENC_H * OUTC; i += 256) aux[i] = X0[i];        // A2s
            if (tid < OUTC) aux[600 + tid] = X1[tid];                             // a2s
        }

        #pragma unroll
        for (int pass = 0; pass < 2; pass++) {
            __syncthreads();   // As/Bs reads done (pass 0) / prior hbuf reads done (pass 1); aux visible
            if ((tr >> 6) == pass) {
                int lr = tr & 63;
                #pragma unroll
                for (int i = 0; i < 8; i++) {
                    float o[8];
                    #pragma unroll
                    for (int j = 0; j < 8; j++) o[j] = gelu(acc[i][j] + bb[tc + j]);
                    *(float4*)&hbuf[(lr + i) * HS + tc]     = make_float4(o[0], o[1], o[2], o[3]);
                    *(float4*)&hbuf[(lr + i) * HS + tc + 4] = make_float4(o[4], o[5], o[6], o[7]);
                }
            }
            __syncthreads();

            int r = tid >> 2, q = tid & 3;          // 4 threads per row
            if (EPI == 1) {
                const float* W3s = aux;
                const float* b3s = aux + 2560;
                float lac[5] = {0.f, 0.f, 0.f, 0.f, 0.f};
                for (int k = 0; k < 128; k++) {
                    float v = hbuf[r * HS + k];
                    const float* w = W3s + k * NATOMS + q * 5;
                    #pragma unroll
                    for (int j = 0; j < 5; j++) lac[j] += v * w[j];
                }
                float best = -1e30f; int bidx = 0;
                #pragma unroll
                for (int j = 0; j < 5; j++) {
                    int col = q * 5 + j;
                    float lg = lac[j] + b3s[col];
                    if (lg > best) { best = lg; bidx = col; }
                }
                #pragma unroll
                for (int o = 1; o <= 2; o <<= 1) {
                    float ob = __shfl_xor_sync(0xffffffffu, best, o);
                    int   oi = __shfl_xor_sync(0xffffffffu, bidx, o);
                    if (ob > best || (ob == best && oi < bidx)) { best = ob; bidx = oi; }
                }
                if (q == 0) g_ids[mt * 128 + pass * 64 + r] = bidx;
            }
            if (EPI == 2) {
                const float* A2s = aux;
                const float* a2s = aux + 600;
                if (q < 3) {
                    float s0 = 0.f, s1 = 0.f;
                    for (int k = 0; k < ENC_H; k++) {
                        float v = hbuf[r * HS + k];
                        const float* w = A2s + k * OUTC + q * 2;
                        s0 += v * w[0]; s1 += v * w[1];
                    }
                    float alpha = X2[0];
                    int node = mt * 128 + pass * 64 + r;
                    int c0 = q * 2, c1 = q * 2 + 1;
                    float t0 = gelu(s0 + a2s[c0]);
                    float u0 = tanhf(alpha * t0) * X3[c0] + X4[c0];
                    OUT[(size_t)node * OUTC + c0] = tanhf(u0);
                    float t1 = gelu(s1 + a2s[c1]);
                    float u1 = tanhf(alpha * t1) * X3[c1] + X4[c1];
                    OUT[(size_t)node * OUTC + c1] = tanhf(u1);
                }
            }
        }
    }
}

// ---------------- K8: aggregation -> z, coords ----------------
__global__ void __launch_bounds__(256)
k_agg(const float* __restrict__ b_msg, const float* __restrict__ w_coor,
      const float* __restrict__ coords, float* __restrict__ out_z,
      float* __restrict__ out_coors) {
    __shared__ float TWs[NATOMS * DIM];
    __shared__ float wcs[DIM * 3];
    __shared__ float bms[DIM];
    __shared__ int   hist[8][NATOMS];
    int tid = threadIdx.x;
    for (int i = tid; i < NATOMS * DIM; i += 256) TWs[i] = g_TW[i];
    for (int i = tid; i < DIM * 3; i += 256)      wcs[i] = w_coor[i];
    for (int i = tid; i < DIM; i += 256)          bms[i] = b_msg[i];
    __syncthreads();

    int warp = tid >> 5, lane = tid & 31;
    int* myhist = hist[warp];
    int wglobal = blockIdx.x * 8 + warp;
    int wstride = gridDim.x * 8;
    int d0 = lane * 4;

    for (int node = wglobal; node < NT; node += wstride) {
        if (lane < NATOMS) myhist[lane] = 0;
        __syncwarp();
        int base = node & ~(NPER - 1);
        int deg = 0;
        #pragma unroll
        for (int half = 0; half < 2; half++) {
            int w = lane + half * 32;
            unsigned m = g_mask[(size_t)node * 64 + w];
            deg += __popc(m);
            while (m) {
                int b = __ffs(m) - 1;
                m &= m - 1;
                int id = g_ids[base + w * 32 + b];
                atomicAdd(&myhist[id], 1);
            }
        }
        deg = __reduce_add_sync(0xffffffffu, deg);
        __syncwarp();
        float invdeg = 1.0f / (float)(deg > 0 ? deg : 1);
        int myid = g_ids[node];

        float4 s = make_float4(0.f, 0.f, 0.f, 0.f);
        #pragma unroll
        for (int a = 0; a < NATOMS; a++) {
            float cf = (float)myhist[a];
            float4 t = *(const float4*)&TWs[a * DIM + d0];
            s.x += cf * t.x; s.y += cf * t.y; s.z += cf * t.z; s.w += cf * t.w;
        }
        float4 own = *(const float4*)&TWs[myid * DIM + d0];
        float h0 = gelu(bms[d0 + 0] + own.x + invdeg * s.x);
        float h1 = gelu(bms[d0 + 1] + own.y + invdeg * s.y);
        float h2 = gelu(bms[d0 + 2] + own.z + invdeg * s.z);
        float h3 = gelu(bms[d0 + 3] + own.w + invdeg * s.w);
        *(float4*)&out_z[(size_t)node * DIM + d0] = make_float4(h0, h1, h2, h3);

        float p0 = h0 * wcs[(d0 + 0) * 3 + 0] + h1 * wcs[(d0 + 1) * 3 + 0]
                 + h2 * wcs[(d0 + 2) * 3 + 0] + h3 * wcs[(d0 + 3) * 3 + 0];
        float p1 = h0 * wcs[(d0 + 0) * 3 + 1] + h1 * wcs[(d0 + 1) * 3 + 1]
                 + h2 * wcs[(d0 + 2) * 3 + 1] + h3 * wcs[(d0 + 3) * 3 + 1];
        float p2 = h0 * wcs[(d0 + 0) * 3 + 2] + h1 * wcs[(d0 + 1) * 3 + 2]
                 + h2 * wcs[(d0 + 2) * 3 + 2] + h3 * wcs[(d0 + 3) * 3 + 2];
        #pragma unroll
        for (int o = 16; o > 0; o >>= 1) {
            p0 += __shfl_xor_sync(0xffffffffu, p0, o);
            p1 += __shfl_xor_sync(0xffffffffu, p1, o);
            p2 += __shfl_xor_sync(0xffffffffu, p2, o);
        }
        if (lane == 0) {
            out_coors[(size_t)node * 3 + 0] = coords[(size_t)node * 3 + 0] + tanhf(p0);
            out_coors[(size_t)node * 3 + 1] = coords[(size_t)node * 3 + 1] + tanhf(p1);
            out_coors[(size_t)node * 3 + 2] = coords[(size_t)node * 3 + 2] + tanhf(p2);
        }
    }
}

// ---------------- launch ----------------
#define SMEM0 (4096 * 4)
#define SMEM1 ((64 * 132 + 2580) * 4)
#define SMEM2 ((64 * 132 + 606) * 4)
extern "C" void kernel_launch(void* const* d_in, const int* in_sizes, int n_in,
                              void* d_out, int out_size) {
    const float* x_res     = (const float*)d_in[0];
    const float* coords    = (const float*)d_in[1];
    const int*   edge_idx  = (const int*)  d_in[2];
    const float* bn_gamma  = (const float*)d_in[4];
    const float* bn_beta   = (const float*)d_in[5];
    const float* W1        = (const float*)d_in[6];
    const float* b1        = (const float*)d_in[7];
    const float* W2        = (const float*)d_in[8];
    const float* b2        = (const float*)d_in[9];
    const float* W3        = (const float*)d_in[10];
    const float* b3        = (const float*)d_in[11];
    const float* embed     = (const float*)d_in[12];
    const float* W_msg     = (const float*)d_in[13];
    const float* b_msg     = (const float*)d_in[14];
    const float* w_coor    = (const float*)d_in[15];
    const float* A1        = (const float*)d_in[16];
    const float* a1        = (const float*)d_in[17];
    const float* A2        = (const float*)d_in[18];
    const float* a2        = (const float*)d_in[19];
    const float* dyt_alpha = (const float*)d_in[20];
    const float* dyt_w     = (const float*)d_in[21];
    const float* dyt_b     = (const float*)d_in[22];
    int E = in_sizes[2] / 2;

    float* out        = (float*)d_out;
    float* out_angles = out;
    float* out_z      = out + (size_t)NT * OUTC;
    float* out_coors  = out_z + (size_t)NT * DIM;

    float* h1p;  cudaGetSymbolAddress((void**)&h1p,  g_h1);
    float* W1fp; cudaGetSymbolAddress((void**)&W1fp, g_W1f);
    float* b1fp; cudaGetSymbolAddress((void**)&b1fp, g_b1f);
    float* A1pp; cudaGetSymbolAddress((void**)&A1pp, g_A1p);
    float* a1pp; cudaGetSymbolAddress((void**)&a1pp, g_a1p);

    cudaFuncSetAttribute((const void*)k_gemm<0>,
                         cudaFuncAttributeMaxDynamicSharedMemorySize, SMEM0);
    cudaFuncSetAttribute((const void*)k_gemm<1>,
                         cudaFuncAttributeMaxDynamicSharedMemorySize, SMEM1);
    cudaFuncSetAttribute((const void*)k_gemm<2>,
                         cudaFuncAttributeMaxDynamicSharedMemorySize, SMEM2);

    k_zero<<<4096, 512>>>();
    k_bn_stats<<<NT / 128, 256>>>(x_res);
    k_fold<<<H1DIM, IN_C>>>(W1, b1, bn_gamma, bn_beta);
    k_small<<<384, 256>>>(embed, W_msg, A1, a1);
    k_edges<<<(E + 255) / 256, 256>>>(edge_idx, E);

    // GEMM1: h1 = gelu(xn @ W1f + b1f)   [32768 x 256]
    k_gemm<0><<<dim3(2, 256), 256, SMEM0>>>(
        x_res, W1fp, b1fp, h1p,
        nullptr, nullptr, nullptr, nullptr, nullptr, nullptr, IN_C, H1DIM);
    // GEMM2 fused: h2 tile -> logits -> argmax -> g_ids
    k_gemm<1><<<dim3(1, 256), 256, SMEM1>>>(
        h1p, W2, b2, nullptr,
        W3, b3, nullptr, nullptr, nullptr, nullptr, H1DIM, DIM);
    // z, coords
    k_agg<<<512, 256>>>(b_msg, w_coor, coords, out_z, out_coors);
    // GEMM3 fused: t1 tile -> angles head -> out_angles
    k_gemm<2><<<dim3(1, 256), 256, SMEM2>>>(
        out_z, A1pp, a1pp, nullptr,
        A2, a2, dyt_alpha, dyt_w, dyt_b, out_angles, DIM, 128);
}

// round 13
// speedup vs baseline: 1.0303x; 1.0303x over previous
#include <cuda_runtime.h>
#include <cuda_bf16.h>
#include <math.h>
#include <stdint.h>

// ---------------- problem constants ----------------
#define NT      32768
#define NPER    2048
#define IN_C    256
#define DIM     128
#define H1DIM   256
#define NATOMS  20
#define ENC_H   100
#define OUTC    6
#define MASK_WORDS (NT * 64)

// ---------------- scratch ----------------
__device__ unsigned g_mask[MASK_WORDS];
__device__ float    g_stats[2 * IN_C];
__device__ int      g_ids[NT];
__device__ float    g_b1f[H1DIM];
__device__ float    g_W1f[IN_C * H1DIM];   // BN-folded W1 (GEMM1 B operand)
__device__ float    g_TW[NATOMS * DIM];
__device__ float    g_A1p[128 * 128];      // A1 zero-padded 100->128 cols
__device__ float    g_a1p[128];
__device__ float    g_h1[(size_t)NT * H1DIM];

// ---------------- helpers ----------------
__device__ __forceinline__ float gelu(float x) {
    return 0.5f * x * (1.0f + erff(x * 0.70710678118654752f));
}

// ---------------- K_pre1: zero(mask+stats) | TW | padA1  (independent parts) ----------------
// blocks [0,512)        : zero g_mask (each block 4096 words via uint4)
// block  512             : zero g_stats
// blocks [513,513+320)   : TW = embed[0:20] @ W_msg (warp per output)
// blocks [833,833+64)    : pad A1 -> g_A1p, a1 -> g_a1p
__global__ void k_pre1(const float* __restrict__ embed, const float* __restrict__ Wm,
                       const float* __restrict__ A1, const float* __restrict__ a1) {
    int b = blockIdx.x, tid = threadIdx.x;
    if (b < 512) {
        uint4* dst = (uint4*)g_mask + (size_t)b * 1024;
        uint4 z = make_uint4(0u, 0u, 0u, 0u);
        dst[tid]       = z;
        dst[tid + 256] = z;
        dst[tid + 512] = z;
        dst[tid + 768] = z;
    } else if (b == 512) {
        g_stats[tid]       = 0.0f;
        g_stats[tid + 256] = 0.0f;
    } else if (b < 833) {
        int w = ((b - 513) * 256 + tid) >> 5;
        int lane = tid & 31;
        if (w < NATOMS * DIM) {
            int a = w >> 7, j = w & 127;
            float s = 0.f;
            #pragma unroll
            for (int i = 0; i < 4; i++) {
                int k = lane * 4 + i;
                s += embed[a * DIM + k] * Wm[k * DIM + j];
            }
            #pragma unroll
            for (int o = 16; o > 0; o >>= 1) s += __shfl_xor_sync(0xffffffffu, s, o);
            if (lane == 0) g_TW[w] = s;
        }
    } else {
        int t = (b - 833) * 256 + tid;
        if (t < 128 * 128) {
            int k = t >> 7, j = t & 127;
            g_A1p[t] = (j < ENC_H) ? A1[k * ENC_H + j] : 0.0f;
            if (k == 0) g_a1p[j] = (j < ENC_H) ? a1[j] : 0.0f;
        }
    }
}

// ---------------- K_pre2: bn_stats | edge scatter  (both depend only on K_pre1 zeroing) ----------------
// blocks [0,256)  : BN stats (atomicAdd into g_stats)
// blocks [256,..) : edge scatter (atomicOr into g_mask)
__global__ void k_pre2(const float* __restrict__ x, const int* __restrict__ ei, int E) {
    int b = blockIdx.x, tid = threadIdx.x;
    if (b < 256) {
        int c  = tid;
        int r0 = b * 128;
        float s = 0.f, q = 0.f;
        #pragma unroll 4
        for (int r = 0; r < 128; r++) {
            float v = x[(size_t)(r0 + r) * IN_C + c];
            s += v; q += v * v;
        }
        atomicAdd(&g_stats[c], s);
        atomicAdd(&g_stats[IN_C + c], q);
    } else {
        int e = (b - 256) * 256 + tid;
        if (e < E) {
            int s = ei[e];
            int d = ei[E + e];
            if ((s >> 11) == (d >> 11)) {
                unsigned bit = ((unsigned)s << 11) + (unsigned)(d & (NPER - 1));
                atomicOr(&g_mask[bit >> 5], 1u << (bit & 31));
            }
        }
    }
}

// ---------------- K_pre3: fold BN into W1 ----------------
__global__ void k_fold(const float* __restrict__ W1, const float* __restrict__ b1,
                       const float* __restrict__ gamma, const float* __restrict__ beta) {
    int j = blockIdx.x;      // output col
    int c = threadIdx.x;     // input channel
    float mean = g_stats[c] * (1.0f / NT);
    float var  = g_stats[IN_C + c] * (1.0f / NT) - mean * mean;
    float inv  = rsqrtf(var + 1e-5f);
    float sc   = gamma[c] * inv;
    float sh   = beta[c] - mean * sc;
    float w    = W1[c * H1DIM + j];
    g_W1f[c * H1DIM + j] = sc * w;
    __shared__ float red[256];
    red[c] = sh * w;
    __syncthreads();
    for (int o = 128; o > 0; o >>= 1) {
        if (c < o) red[c] += red[c + o];
        __syncthreads();
    }
    if (c == 0) g_b1f[j] = b1[j] + red[0];
}

// ---------------- fused SGEMM (BM=BN=128, BK=16, TM=TN=8, reg double-buffer) ----------------
// EPI 0: C = gelu(A@B + bias)            (GEMM1 -> g_h1)
// EPI 1: h2 tile -> smem; logits = h2@W3+b3; argmax -> g_ids
// EPI 2: t1 tile -> smem; t2 = gelu(t1[:,0:100]@A2+a2); dyt; tanh -> OUT angles
template<int EPI>
__global__ void __launch_bounds__(256)
k_gemm(const float* __restrict__ A, const float* __restrict__ B,
       const float* __restrict__ bias, float* __restrict__ C,
       const float* __restrict__ X0, const float* __restrict__ X1,
       const float* __restrict__ X2, const float* __restrict__ X3,
       const float* __restrict__ X4, float* __restrict__ OUT,
       int K, int N) {
    extern __shared__ float sm[];
    float* As   = sm;              // 16*128
    float* Bs   = sm + 2048;       // 16*128
    float* hbuf = sm + 4096;       // 128*129 (EPI 1/2)
    float* aux  = sm + 4096 + 128 * 129;

    int tid = threadIdx.x;
    int nt = blockIdx.x, mt = blockIdx.y;
    const float* Ab = A + (size_t)mt * 128 * K;
    const float* Bb = B + nt * 128;
    const float* bb = bias + nt * 128;

    int arow = tid >> 1, acol = (tid & 1) * 8;
    int brow = tid >> 4, bcol = (tid & 15) * 8;
    int tr = (tid >> 4) * 8, tc = (tid & 15) * 8;

    float acc[8][8];
    #pragma unroll
    for (int i = 0; i < 8; i++)
        #pragma unroll
        for (int j = 0; j < 8; j++) acc[i][j] = 0.f;

    // prefetch first k-tile into registers
    float4 pav0 = *(const float4*)(Ab + (size_t)arow * K + acol);
    float4 pav1 = *(const float4*)(Ab + (size_t)arow * K + acol + 4);
    float4 pbv0 = *(const float4*)(Bb + (size_t)brow * N + bcol);
    float4 pbv1 = *(const float4*)(Bb + (size_t)brow * N + bcol + 4);

    for (int k0 = 0; k0 < K; k0 += 16) {
        As[(acol + 0) * 128 + arow] = pav0.x;
        As[(acol + 1) * 128 + arow] = pav0.y;
        As[(acol + 2) * 128 + arow] = pav0.z;
        As[(acol + 3) * 128 + arow] = pav0.w;
        As[(acol + 4) * 128 + arow] = pav1.x;
        As[(acol + 5) * 128 + arow] = pav1.y;
        As[(acol + 6) * 128 + arow] = pav1.z;
        As[(acol + 7) * 128 + arow] = pav1.w;
        *(float4*)&Bs[brow * 128 + bcol]     = pbv0;
        *(float4*)&Bs[brow * 128 + bcol + 4] = pbv1;
        __syncthreads();

        if (k0 + 16 < K) {
            pav0 = *(const float4*)(Ab + (size_t)arow * K + k0 + 16 + acol);
            pav1 = *(const float4*)(Ab + (size_t)arow * K + k0 + 16 + acol + 4);
            pbv0 = *(const float4*)(Bb + (size_t)(k0 + 16 + brow) * N + bcol);
            pbv1 = *(const float4*)(Bb + (size_t)(k0 + 16 + brow) * N + bcol + 4);
        }

        #pragma unroll
        for (int kk = 0; kk < 16; kk++) {
            float4 a0 = *(const float4*)&As[kk * 128 + tr];
            float4 a1 = *(const float4*)&As[kk * 128 + tr + 4];
            float4 b0 = *(const float4*)&Bs[kk * 128 + tc];
            float4 b1 = *(const float4*)&Bs[kk * 128 + tc + 4];
            float ra[8] = {a0.x, a0.y, a0.z, a0.w, a1.x, a1.y, a1.z, a1.w};
            float rb[8] = {b0.x, b0.y, b0.z, b0.w, b1.x, b1.y, b1.z, b1.w};
            #pragma unroll
            for (int i = 0; i < 8; i++)
                #pragma unroll
                for (int j = 0; j < 8; j++) acc[i][j] += ra[i] * rb[j];
        }
        __syncthreads();
    }

    // ---- epilogue ----
    if (EPI == 0) {
        #pragma unroll
        for (int i = 0; i < 8; i++) {
            int row = tr + i;
            float o[8];
            #pragma unroll
            for (int j = 0; j < 8; j++) o[j] = gelu(acc[i][j] + bb[tc + j]);
            float* crow = C + (size_t)(mt * 128 + row) * N + nt * 128 + tc;
            *(float4*)(crow)     = make_float4(o[0], o[1], o[2], o[3]);
            *(float4*)(crow + 4) = make_float4(o[4], o[5], o[6], o[7]);
        }
    } else {
        #pragma unroll
        for (int i = 0; i < 8; i++)
            #pragma unroll
            for (int j = 0; j < 8; j++)
                hbuf[(tr + i) * 129 + tc + j] = gelu(acc[i][j] + bb[tc + j]);

        if (EPI == 1) {
            float* W3s  = aux;                 // 128*20
            float* b3s  = aux + 2560;          // 20
            float* redf = aux + 2580;          // 256
            int*   redi = (int*)(aux + 2836);  // 256
            for (int i = tid; i < 128 * NATOMS; i += 256) W3s[i] = X0[i];
            if (tid < NATOMS) b3s[tid] = X1[tid];
            __syncthreads();

            int r = tid >> 1, half = tid & 1;
            float lac[10];
            #pragma unroll
            for (int j = 0; j < 10; j++) lac[j] = 0.f;
            for (int k = 0; k < 128; k++) {
                float v = hbuf[r * 129 + k];
                const float* w = W3s + k * NATOMS + half * 10;
                #pragma unroll
                for (int j = 0; j < 10; j++) lac[j] += v * w[j];
            }
            float best = -1e30f; int bidx = 0;
            #pragma unroll
            for (int j = 0; j < 10; j++) {
                int col = half * 10 + j;
                float lg = lac[j] + b3s[col];
                if (lg > best) { best = lg; bidx = col; }
            }
            redf[tid] = best; redi[tid] = bidx;
            __syncthreads();
            if (half == 0) {
                float f0 = redf[tid], f1 = redf[tid + 1];
                int id = (f1 > f0) ? redi[tid + 1] : redi[tid];
                g_ids[mt * 128 + r] = id;
            }
        }
        if (EPI == 2) {
            float* A2s = aux;           // 100*6
            float* a2s = aux + 600;     // 6
            for (int i = tid; i < ENC_H * OUTC; i += 256) A2s[i] = X0[i];
            if (tid < OUTC) a2s[tid] = X1[tid];
            __syncthreads();

            int r = tid >> 1, q0 = (tid & 1) * 3;
            float a3[3] = {0.f, 0.f, 0.f};
            for (int k = 0; k < ENC_H; k++) {
                float v = hbuf[r * 129 + k];
                const float* w = A2s + k * OUTC + q0;
                a3[0] += v * w[0]; a3[1] += v * w[1]; a3[2] += v * w[2];
            }
            float alpha = X2[0];
            int node = mt * 128 + r;
            #pragma unroll
            for (int c = 0; c < 3; c++) {
                int ch = q0 + c;
                float t = gelu(a3[c] + a2s[ch]);
                float u = tanhf(alpha * t) * X3[ch] + X4[ch];
                OUT[(size_t)node * OUTC + ch] = tanhf(u);
            }
        }
    }
}

// ---------------- K8: aggregation -> z, coords ----------------
__global__ void __launch_bounds__(256)
k_agg(const float* __restrict__ b_msg, const float* __restrict__ w_coor,
      const float* __restrict__ coords, float* __restrict__ out_z,
      float* __restrict__ out_coors) {
    __shared__ float TWs[NATOMS * DIM];
    __shared__ float wcs[DIM * 3];
    __shared__ float bms[DIM];
    __shared__ int   hist[8][NATOMS];
    int tid = threadIdx.x;
    for (int i = tid; i < NATOMS * DIM; i += 256) TWs[i] = g_TW[i];
    for (int i = tid; i < DIM * 3; i += 256)      wcs[i] = w_coor[i];
    for (int i = tid; i < DIM; i += 256)          bms[i] = b_msg[i];
    __syncthreads();

    int warp = tid >> 5, lane = tid & 31;
    int* myhist = hist[warp];
    int wglobal = blockIdx.x * 8 + warp;
    int wstride = gridDim.x * 8;
    int d0 = lane * 4;

    for (int node = wglobal; node < NT; node += wstride) {
        if (lane < NATOMS) myhist[lane] = 0;
        __syncwarp();
        int base = node & ~(NPER - 1);
        int deg = 0;
        #pragma unroll
        for (int half = 0; half < 2; half++) {
            int w = lane + half * 32;
            unsigned m = g_mask[(size_t)node * 64 + w];
            deg += __popc(m);
            while (m) {
                int b = __ffs(m) - 1;
                m &= m - 1;
                int id = g_ids[base + w * 32 + b];
                atomicAdd(&myhist[id], 1);
            }
        }
        deg = __reduce_add_sync(0xffffffffu, deg);
        __syncwarp();
        float invdeg = 1.0f / (float)(deg > 0 ? deg : 1);
        int myid = g_ids[node];

        float4 s = make_float4(0.f, 0.f, 0.f, 0.f);
        #pragma unroll
        for (int a = 0; a < NATOMS; a++) {
            float cf = (float)myhist[a];
            float4 t = *(const float4*)&TWs[a * DIM + d0];
            s.x += cf * t.x; s.y += cf * t.y; s.z += cf * t.z; s.w += cf * t.w;
        }
        float4 own = *(const float4*)&TWs[myid * DIM + d0];
        float h0 = gelu(bms[d0 + 0] + own.x + invdeg * s.x);
        float h1 = gelu(bms[d0 + 1] + own.y + invdeg * s.y);
        float h2 = gelu(bms[d0 + 2] + own.z + invdeg * s.z);
        float h3 = gelu(bms[d0 + 3] + own.w + invdeg * s.w);
        *(float4*)&out_z[(size_t)node * DIM + d0] = make_float4(h0, h1, h2, h3);

        float p0 = h0 * wcs[(d0 + 0) * 3 + 0] + h1 * wcs[(d0 + 1) * 3 + 0]
                 + h2 * wcs[(d0 + 2) * 3 + 0] + h3 * wcs[(d0 + 3) * 3 + 0];
        float p1 = h0 * wcs[(d0 + 0) * 3 + 1] + h1 * wcs[(d0 + 1) * 3 + 1]
                 + h2 * wcs[(d0 + 2) * 3 + 1] + h3 * wcs[(d0 + 3) * 3 + 1];
        float p2 = h0 * wcs[(d0 + 0) * 3 + 2] + h1 * wcs[(d0 + 1) * 3 + 2]
                 + h2 * wcs[(d0 + 2) * 3 + 2] + h3 * wcs[(d0 + 3) * 3 + 2];
        #pragma unroll
        for (int o = 16; o > 0; o >>= 1) {
            p0 += __shfl_xor_sync(0xffffffffu, p0, o);
            p1 += __shfl_xor_sync(0xffffffffu, p1, o);
            p2 += __shfl_xor_sync(0xffffffffu, p2, o);
        }
        if (lane == 0) {
            out_coors[(size_t)node * 3 + 0] = coords[(size_t)node * 3 + 0] + tanhf(p0);
            out_coors[(size_t)node * 3 + 1] = coords[(size_t)node * 3 + 1] + tanhf(p1);
            out_coors[(size_t)node * 3 + 2] = coords[(size_t)node * 3 + 2] + tanhf(p2);
        }
    }
}

// ---------------- launch ----------------
#define SMEM0 (4096 * 4)
#define SMEM1 ((4096 + 128 * 129 + 3092) * 4)
#define SMEM2 ((4096 + 128 * 129 + 640) * 4)
extern "C" void kernel_launch(void* const* d_in, const int* in_sizes, int n_in,
                              void* d_out, int out_size) {
    const float* x_res     = (const float*)d_in[0];
    const float* coords    = (const float*)d_in[1];
    const int*   edge_idx  = (const int*)  d_in[2];
    const float* bn_gamma  = (const float*)d_in[4];
    const float* bn_beta   = (const float*)d_in[5];
    const float* W1        = (const float*)d_in[6];
    const float* b1        = (const float*)d_in[7];
    const float* W2        = (const float*)d_in[8];
    const float* b2        = (const float*)d_in[9];
    const float* W3        = (const float*)d_in[10];
    const float* b3        = (const float*)d_in[11];
    const float* embed     = (const float*)d_in[12];
    const float* W_msg     = (const float*)d_in[13];
    const float* b_msg     = (const float*)d_in[14];
    const float* w_coor    = (const float*)d_in[15];
    const float* A1        = (const float*)d_in[16];
    const float* a1        = (const float*)d_in[17];
    const float* A2        = (const float*)d_in[18];
    const float* a2        = (const float*)d_in[19];
    const float* dyt_alpha = (const float*)d_in[20];
    const float* dyt_w     = (const float*)d_in[21];
    const float* dyt_b     = (const float*)d_in[22];
    int E = in_sizes[2] / 2;

    float* out        = (float*)d_out;
    float* out_angles = out;
    float* out_z      = out + (size_t)NT * OUTC;
    float* out_coors  = out_z + (size_t)NT * DIM;

    float* h1p;  cudaGetSymbolAddress((void**)&h1p,  g_h1);
    float* W1fp; cudaGetSymbolAddress((void**)&W1fp, g_W1f);
    float* b1fp; cudaGetSymbolAddress((void**)&b1fp, g_b1f);
    float* A1pp; cudaGetSymbolAddress((void**)&A1pp, g_A1p);
    float* a1pp; cudaGetSymbolAddress((void**)&a1pp, g_a1p);

    cudaFuncSetAttribute((const void*)k_gemm<0>,
                         cudaFuncAttributeMaxDynamicSharedMemorySize, SMEM0);
    cudaFuncSetAttribute((const void*)k_gemm<1>,
                         cudaFuncAttributeMaxDynamicSharedMemorySize, SMEM1);
    cudaFuncSetAttribute((const void*)k_gemm<2>,
                         cudaFuncAttributeMaxDynamicSharedMemorySize, SMEM2);

    // preproc: 3 launches instead of 5
    k_pre1<<<897, 256>>>(embed, W_msg, A1, a1);
    k_pre2<<<256 + (E + 255) / 256, 256>>>(x_res, edge_idx, E);
    k_fold<<<H1DIM, IN_C>>>(W1, b1, bn_gamma, bn_beta);

    // GEMM1: h1 = gelu(xn @ W1f + b1f)   [32768 x 256]
    k_gemm<0><<<dim3(2, 256), 256, SMEM0>>>(
        x_res, W1fp, b1fp, h1p,
        nullptr, nullptr, nullptr, nullptr, nullptr, nullptr, IN_C, H1DIM);
    // GEMM2 fused: h2 tile -> logits -> argmax -> g_ids
    k_gemm<1><<<dim3(1, 256), 256, SMEM1>>>(
        h1p, W2, b2, nullptr,
        W3, b3, nullptr, nullptr, nullptr, nullptr, H1DIM, DIM);
    // z, coords
    k_agg<<<512, 256>>>(b_msg, w_coor, coords, out_z, out_coors);
    // GEMM3 fused: t1 tile -> angles head -> out_angles
    k_gemm<2><<<dim3(1, 256), 256, SMEM2>>>(
        out_z, A1pp, a1pp, nullptr,
        A2, a2, dyt_alpha, dyt_w, dyt_b, out_angles, DIM, 128);
}

// round 16
// speedup vs baseline: 1.1835x; 1.1487x over previous
#include <cuda_runtime.h>
#include <cuda_bf16.h>
#include <math.h>
#include <stdint.h>

// ---------------- problem constants ----------------
#define NT      32768
#define NPER    2048
#define IN_C    256
#define DIM     128
#define H1DIM   256
#define NATOMS  20
#define ENC_H   100
#define OUTC    6
#define MASK_WORDS (NT * 64)

// ---------------- scratch ----------------
__device__ unsigned g_mask[MASK_WORDS];
__device__ float    g_stats[2 * IN_C];
__device__ int      g_ids[NT];
__device__ float    g_b1f[H1DIM];
__device__ float    g_W1f[IN_C * H1DIM];   // BN-folded W1 (GEMM1 B operand)
__device__ float    g_TW[NATOMS * DIM];
__device__ float    g_A1p[128 * 128];      // A1 zero-padded 100->128 cols
__device__ float    g_a1p[128];
__device__ float    g_h1[(size_t)NT * H1DIM];

// ---------------- helpers ----------------
__device__ __forceinline__ float gelu(float x) {
    return 0.5f * x * (1.0f + erff(x * 0.70710678118654752f));
}

// ---------------- K_pre1: zero(mask+stats) | TW | padA1 ----------------
__global__ void k_pre1(const float* __restrict__ embed, const float* __restrict__ Wm,
                       const float* __restrict__ A1, const float* __restrict__ a1) {
    int b = blockIdx.x, tid = threadIdx.x;
    if (b < 512) {
        uint4* dst = (uint4*)g_mask + (size_t)b * 1024;
        uint4 z = make_uint4(0u, 0u, 0u, 0u);
        dst[tid]       = z;
        dst[tid + 256] = z;
        dst[tid + 512] = z;
        dst[tid + 768] = z;
    } else if (b == 512) {
        g_stats[tid]       = 0.0f;
        g_stats[tid + 256] = 0.0f;
    } else if (b < 833) {
        int w = ((b - 513) * 256 + tid) >> 5;
        int lane = tid & 31;
        if (w < NATOMS * DIM) {
            int a = w >> 7, j = w & 127;
            float s = 0.f;
            #pragma unroll
            for (int i = 0; i < 4; i++) {
                int k = lane * 4 + i;
                s += embed[a * DIM + k] * Wm[k * DIM + j];
            }
            #pragma unroll
            for (int o = 16; o > 0; o >>= 1) s += __shfl_xor_sync(0xffffffffu, s, o);
            if (lane == 0) g_TW[w] = s;
        }
    } else {
        int t = (b - 833) * 256 + tid;
        if (t < 128 * 128) {
            int k = t >> 7, j = t & 127;
            g_A1p[t] = (j < ENC_H) ? A1[k * ENC_H + j] : 0.0f;
            if (k == 0) g_a1p[j] = (j < ENC_H) ? a1[j] : 0.0f;
        }
    }
}

// ---------------- K_pre2: bn_stats | edge scatter ----------------
__global__ void k_pre2(const float* __restrict__ x, const int* __restrict__ ei, int E) {
    int b = blockIdx.x, tid = threadIdx.x;
    if (b < 256) {
        int c  = tid;
        int r0 = b * 128;
        float s = 0.f, q = 0.f;
        #pragma unroll 4
        for (int r = 0; r < 128; r++) {
            float v = x[(size_t)(r0 + r) * IN_C + c];
            s += v; q += v * v;
        }
        atomicAdd(&g_stats[c], s);
        atomicAdd(&g_stats[IN_C + c], q);
    } else {
        int e = (b - 256) * 256 + tid;
        if (e < E) {
            int s = ei[e];
            int d = ei[E + e];
            if ((s >> 11) == (d >> 11)) {
                unsigned bit = ((unsigned)s << 11) + (unsigned)(d & (NPER - 1));
                atomicOr(&g_mask[bit >> 5], 1u << (bit & 31));
            }
        }
    }
}

// ---------------- K_pre3: fold BN into W1 ----------------
__global__ void k_fold(const float* __restrict__ W1, const float* __restrict__ b1,
                       const float* __restrict__ gamma, const float* __restrict__ beta) {
    int j = blockIdx.x;      // output col
    int c = threadIdx.x;     // input channel
    float mean = g_stats[c] * (1.0f / NT);
    float var  = g_stats[IN_C + c] * (1.0f / NT) - mean * mean;
    float inv  = rsqrtf(var + 1e-5f);
    float sc   = gamma[c] * inv;
    float sh   = beta[c] - mean * sc;
    float w    = W1[c * H1DIM + j];
    g_W1f[c * H1DIM + j] = sc * w;
    __shared__ float red[256];
    red[c] = sh * w;
    __syncthreads();
    for (int o = 128; o > 0; o >>= 1) {
        if (c < o) red[c] += red[c + o];
        __syncthreads();
    }
    if (c == 0) g_b1f[j] = b1[j] + red[0];
}

// ---------------- fused SGEMM (BM=BN=128, BK=16, TM=8, TN=4+4 split cols) ----------------
// Thread (tid) owns rows tr..tr+7 (tr=(tid>>4)*8) and columns
// {c0..c0+3} U {c0+64..c0+67} with c0=(tid&15)*4 — B smem reads are phase-contiguous
// (conflict-free) instead of 32B-strided (2-way conflicted).
// EPI 0: C = gelu(A@B + bias)            (GEMM1 -> g_h1)
// EPI 1: h2 tile -> smem; logits = h2@W3+b3; argmax -> g_ids
// EPI 2: t1 tile -> smem; t2 = gelu(t1[:,0:100]@A2+a2); dyt; tanh -> OUT angles
template<int EPI>
__global__ void __launch_bounds__(256, 2)
k_gemm(const float* __restrict__ A, const float* __restrict__ B,
       const float* __restrict__ bias, float* __restrict__ C,
       const float* __restrict__ X0, const float* __restrict__ X1,
       const float* __restrict__ X2, const float* __restrict__ X3,
       const float* __restrict__ X4, float* __restrict__ OUT,
       int K, int N) {
    extern __shared__ float sm[];
    float* As   = sm;              // 16*128
    float* Bs   = sm + 2048;       // 16*128
    float* hbuf = sm + 4096;       // 128*129 (EPI 1/2)
    float* aux  = sm + 4096 + 128 * 129;

    int tid = threadIdx.x;
    int nt = blockIdx.x, mt = blockIdx.y;
    const float* Ab = A + (size_t)mt * 128 * K;
    const float* Bb = B + nt * 128;
    const float* bb = bias + nt * 128;

    int arow = tid >> 1, acol = (tid & 1) * 8;
    int brow = tid >> 4, bcol = (tid & 15) * 8;
    int tr = (tid >> 4) * 8;
    int c0 = (tid & 15) * 4;       // columns c0..c0+3 and c0+64..c0+67

    float acc[8][8];
    #pragma unroll
    for (int i = 0; i < 8; i++)
        #pragma unroll
        for (int j = 0; j < 8; j++) acc[i][j] = 0.f;

    // prefetch first k-tile into registers
    float4 pav0 = *(const float4*)(Ab + (size_t)arow * K + acol);
    float4 pav1 = *(const float4*)(Ab + (size_t)arow * K + acol + 4);
    float4 pbv0 = *(const float4*)(Bb + (size_t)brow * N + bcol);
    float4 pbv1 = *(const float4*)(Bb + (size_t)brow * N + bcol + 4);

    for (int k0 = 0; k0 < K; k0 += 16) {
        As[(acol + 0) * 128 + arow] = pav0.x;
        As[(acol + 1) * 128 + arow] = pav0.y;
        As[(acol + 2) * 128 + arow] = pav0.z;
        As[(acol + 3) * 128 + arow] = pav0.w;
        As[(acol + 4) * 128 + arow] = pav1.x;
        As[(acol + 5) * 128 + arow] = pav1.y;
        As[(acol + 6) * 128 + arow] = pav1.z;
        As[(acol + 7) * 128 + arow] = pav1.w;
        *(float4*)&Bs[brow * 128 + bcol]     = pbv0;
        *(float4*)&Bs[brow * 128 + bcol + 4] = pbv1;
        __syncthreads();

        if (k0 + 16 < K) {
            pav0 = *(const float4*)(Ab + (size_t)arow * K + k0 + 16 + acol);
            pav1 = *(const float4*)(Ab + (size_t)arow * K + k0 + 16 + acol + 4);
            pbv0 = *(const float4*)(Bb + (size_t)(k0 + 16 + brow) * N + bcol);
            pbv1 = *(const float4*)(Bb + (size_t)(k0 + 16 + brow) * N + bcol + 4);
        }

        #pragma unroll
        for (int kk = 0; kk < 16; kk++) {
            float4 a0 = *(const float4*)&As[kk * 128 + tr];
            float4 a1 = *(const float4*)&As[kk * 128 + tr + 4];
            float4 b0 = *(const float4*)&Bs[kk * 128 + c0];       // contiguous per phase
            float4 b1 = *(const float4*)&Bs[kk * 128 + c0 + 64];  // contiguous per phase
            float ra[8] = {a0.x, a0.y, a0.z, a0.w, a1.x, a1.y, a1.z, a1.w};
            float rb[8] = {b0.x, b0.y, b0.z, b0.w, b1.x, b1.y, b1.z, b1.w};
            #pragma unroll
            for (int i = 0; i < 8; i++)
                #pragma unroll
                for (int j = 0; j < 8; j++) acc[i][j] += ra[i] * rb[j];
        }
        __syncthreads();
    }

    // ---- epilogue ----
    if (EPI == 0) {
        #pragma unroll
        for (int i = 0; i < 8; i++) {
            int row = tr + i;
            float o[8];
            #pragma unroll
            for (int j = 0; j < 4; j++) o[j]     = gelu(acc[i][j]     + bb[c0 + j]);
            #pragma unroll
            for (int j = 0; j < 4; j++) o[4 + j] = gelu(acc[i][4 + j] + bb[c0 + 64 + j]);
            float* crow = C + (size_t)(mt * 128 + row) * N + nt * 128;
            *(float4*)(crow + c0)      = make_float4(o[0], o[1], o[2], o[3]);
            *(float4*)(crow + c0 + 64) = make_float4(o[4], o[5], o[6], o[7]);
        }
    } else {
        #pragma unroll
        for (int i = 0; i < 8; i++) {
            #pragma unroll
            for (int j = 0; j < 4; j++)
                hbuf[(tr + i) * 129 + c0 + j]      = gelu(acc[i][j]     + bb[c0 + j]);
            #pragma unroll
            for (int j = 0; j < 4; j++)
                hbuf[(tr + i) * 129 + c0 + 64 + j] = gelu(acc[i][4 + j] + bb[c0 + 64 + j]);
        }

        if (EPI == 1) {
            float* W3s  = aux;                 // 128*20
            float* b3s  = aux + 2560;          // 20
            float* redf = aux + 2580;          // 256
            int*   redi = (int*)(aux + 2836);  // 256
            for (int i = tid; i < 128 * NATOMS; i += 256) W3s[i] = X0[i];
            if (tid < NATOMS) b3s[tid] = X1[tid];
            __syncthreads();

            int r = tid >> 1, half = tid & 1;
            float lac[10];
            #pragma unroll
            for (int j = 0; j < 10; j++) lac[j] = 0.f;
            for (int k = 0; k < 128; k++) {
                float v = hbuf[r * 129 + k];
                const float* w = W3s + k * NATOMS + half * 10;
                #pragma unroll
                for (int j = 0; j < 10; j++) lac[j] += v * w[j];
            }
            float best = -1e30f; int bidx = 0;
            #pragma unroll
            for (int j = 0; j < 10; j++) {
                int col = half * 10 + j;
                float lg = lac[j] + b3s[col];
                if (lg > best) { best = lg; bidx = col; }
            }
            redf[tid] = best; redi[tid] = bidx;
            __syncthreads();
            if (half == 0) {
                float f0 = redf[tid], f1 = redf[tid + 1];
                int id = (f1 > f0) ? redi[tid + 1] : redi[tid];
                g_ids[mt * 128 + r] = id;
            }
        }
        if (EPI == 2) {
            float* A2s = aux;           // 100*6
            float* a2s = aux + 600;     // 6
            for (int i = tid; i < ENC_H * OUTC; i += 256) A2s[i] = X0[i];
            if (tid < OUTC) a2s[tid] = X1[tid];
            __syncthreads();

            int r = tid >> 1, q0 = (tid & 1) * 3;
            float a3[3] = {0.f, 0.f, 0.f};
            for (int k = 0; k < ENC_H; k++) {
                float v = hbuf[r * 129 + k];
                const float* w = A2s + k * OUTC + q0;
                a3[0] += v * w[0]; a3[1] += v * w[1]; a3[2] += v * w[2];
            }
            float alpha = X2[0];
            int node = mt * 128 + r;
            #pragma unroll
            for (int c = 0; c < 3; c++) {
                int ch = q0 + c;
                float t = gelu(a3[c] + a2s[ch]);
                float u = tanhf(alpha * t) * X3[ch] + X4[ch];
                OUT[(size_t)node * OUTC + ch] = tanhf(u);
            }
        }
    }
}

// ---------------- K8: aggregation -> z, coords ----------------
__global__ void __launch_bounds__(256)
k_agg(const float* __restrict__ b_msg, const float* __restrict__ w_coor,
      const float* __restrict__ coords, float* __restrict__ out_z,
      float* __restrict__ out_coors) {
    __shared__ float TWs[NATOMS * DIM];
    __shared__ float wcs[DIM * 3];
    __shared__ float bms[DIM];
    __shared__ int   hist[8][NATOMS];
    int tid = threadIdx.x;
    for (int i = tid; i < NATOMS * DIM; i += 256) TWs[i] = g_TW[i];
    for (int i = tid; i < DIM * 3; i += 256)      wcs[i] = w_coor[i];
    for (int i = tid; i < DIM; i += 256)          bms[i] = b_msg[i];
    __syncthreads();

    int warp = tid >> 5, lane = tid & 31;
    int* myhist = hist[warp];
    int wglobal = blockIdx.x * 8 + warp;
    int wstride = gridDim.x * 8;
    int d0 = lane * 4;

    for (int node = wglobal; node < NT; node += wstride) {
        if (lane < NATOMS) myhist[lane] = 0;
        __syncwarp();
        int base = node & ~(NPER - 1);
        int deg = 0;
        #pragma unroll
        for (int half = 0; half < 2; half++) {
            int w = lane + half * 32;
            unsigned m = g_mask[(size_t)node * 64 + w];
            deg += __popc(m);
            while (m) {
                int b = __ffs(m) - 1;
                m &= m - 1;
                int id = g_ids[base + w * 32 + b];
                atomicAdd(&myhist[id], 1);
            }
        }
        deg = __reduce_add_sync(0xffffffffu, deg);
        __syncwarp();
        float invdeg = 1.0f / (float)(deg > 0 ? deg : 1);
        int myid = g_ids[node];

        float4 s = make_float4(0.f, 0.f, 0.f, 0.f);
        #pragma unroll
        for (int a = 0; a < NATOMS; a++) {
            float cf = (float)myhist[a];
            float4 t = *(const float4*)&TWs[a * DIM + d0];
            s.x += cf * t.x; s.y += cf * t.y; s.z += cf * t.z; s.w += cf * t.w;
        }
        float4 own = *(const float4*)&TWs[myid * DIM + d0];
        float h0 = gelu(bms[d0 + 0] + own.x + invdeg * s.x);
        float h1 = gelu(bms[d0 + 1] + own.y + invdeg * s.y);
        float h2 = gelu(bms[d0 + 2] + own.z + invdeg * s.z);
        float h3 = gelu(bms[d0 + 3] + own.w + invdeg * s.w);
        *(float4*)&out_z[(size_t)node * DIM + d0] = make_float4(h0, h1, h2, h3);

        float p0 = h0 * wcs[(d0 + 0) * 3 + 0] + h1 * wcs[(d0 + 1) * 3 + 0]
                 + h2 * wcs[(d0 + 2) * 3 + 0] + h3 * wcs[(d0 + 3) * 3 + 0];
        float p1 = h0 * wcs[(d0 + 0) * 3 + 1] + h1 * wcs[(d0 + 1) * 3 + 1]
                 + h2 * wcs[(d0 + 2) * 3 + 1] + h3 * wcs[(d0 + 3) * 3 + 1];
        float p2 = h0 * wcs[(d0 + 0) * 3 + 2] + h1 * wcs[(d0 + 1) * 3 + 2]
                 + h2 * wcs[(d0 + 2) * 3 + 2] + h3 * wcs[(d0 + 3) * 3 + 2];
        #pragma unroll
        for (int o = 16; o > 0; o >>= 1) {
            p0 += __shfl_xor_sync(0xffffffffu, p0, o);
            p1 += __shfl_xor_sync(0xffffffffu, p1, o);
            p2 += __shfl_xor_sync(0xffffffffu, p2, o);
        }
        if (lane == 0) {
            out_coors[(size_t)node * 3 + 0] = coords[(size_t)node * 3 + 0] + tanhf(p0);
            out_coors[(size_t)node * 3 + 1] = coords[(size_t)node * 3 + 1] + tanhf(p1);
            out_coors[(size_t)node * 3 + 2] = coords[(size_t)node * 3 + 2] + tanhf(p2);
        }
    }
}

// ---------------- launch ----------------
#define SMEM0 (4096 * 4)
#define SMEM1 ((4096 + 128 * 129 + 3092) * 4)
#define SMEM2 ((4096 + 128 * 129 + 640) * 4)
extern "C" void kernel_launch(void* const* d_in, const int* in_sizes, int n_in,
                              void* d_out, int out_size) {
    const float* x_res     = (const float*)d_in[0];
    const float* coords    = (const float*)d_in[1];
    const int*   edge_idx  = (const int*)  d_in[2];
    const float* bn_gamma  = (const float*)d_in[4];
    const float* bn_beta   = (const float*)d_in[5];
    const float* W1        = (const float*)d_in[6];
    const float* b1        = (const float*)d_in[7];
    const float* W2        = (const float*)d_in[8];
    const float* b2        = (const float*)d_in[9];
    const float* W3        = (const float*)d_in[10];
    const float* b3        = (const float*)d_in[11];
    const float* embed     = (const float*)d_in[12];
    const float* W_msg     = (const float*)d_in[13];
    const float* b_msg     = (const float*)d_in[14];
    const float* w_coor    = (const float*)d_in[15];
    const float* A1        = (const float*)d_in[16];
    const float* a1        = (const float*)d_in[17];
    const float* A2        = (const float*)d_in[18];
    const float* a2        = (const float*)d_in[19];
    const float* dyt_alpha = (const float*)d_in[20];
    const float* dyt_w     = (const float*)d_in[21];
    const float* dyt_b     = (const float*)d_in[22];
    int E = in_sizes[2] / 2;

    float* out        = (float*)d_out;
    float* out_angles = out;
    float* out_z      = out + (size_t)NT * OUTC;
    float* out_coors  = out_z + (size_t)NT * DIM;

    float* h1p;  cudaGetSymbolAddress((void**)&h1p,  g_h1);
    float* W1fp; cudaGetSymbolAddress((void**)&W1fp, g_W1f);
    float* b1fp; cudaGetSymbolAddress((void**)&b1fp, g_b1f);
    float* A1pp; cudaGetSymbolAddress((void**)&A1pp, g_A1p);
    float* a1pp; cudaGetSymbolAddress((void**)&a1pp, g_a1p);

    cudaFuncSetAttribute((const void*)k_gemm<0>,
                         cudaFuncAttributeMaxDynamicSharedMemorySize, SMEM0);
    cudaFuncSetAttribute((const void*)k_gemm<1>,
                         cudaFuncAttributeMaxDynamicSharedMemorySize, SMEM1);
    cudaFuncSetAttribute((const void*)k_gemm<2>,
                         cudaFuncAttributeMaxDynamicSharedMemorySize, SMEM2);

    // preproc: 3 launches
    k_pre1<<<897, 256>>>(embed, W_msg, A1, a1);
    k_pre2<<<256 + (E + 255) / 256, 256>>>(x_res, edge_idx, E);
    k_fold<<<H1DIM, IN_C>>>(W1, b1, bn_gamma, bn_beta);

    // GEMM1: h1 = gelu(xn @ W1f + b1f)   [32768 x 256]
    k_gemm<0><<<dim3(2, 256), 256, SMEM0>>>(
        x_res, W1fp, b1fp, h1p,
        nullptr, nullptr, nullptr, nullptr, nullptr, nullptr, IN_C, H1DIM);
    // GEMM2 fused: h2 tile -> logits -> argmax -> g_ids
    k_gemm<1><<<dim3(1, 256), 256, SMEM1>>>(
        h1p, W2, b2, nullptr,
        W3, b3, nullptr, nullptr, nullptr, nullptr, H1DIM, DIM);
    // z, coords
    k_agg<<<512, 256>>>(b_msg, w_coor, coords, out_z, out_coors);
    // GEMM3 fused: t1 tile -> angles head -> out_angles
    k_gemm<2><<<dim3(1, 256), 256, SMEM2>>>(
        out_z, A1pp, a1pp, nullptr,
        A2, a2, dyt_alpha, dyt_w, dyt_b, out_angles, DIM, 128);
}